// round 2
// baseline (speedup 1.0000x reference)
#include <cuda_runtime.h>

// LSEP loss: log1p( sum_i [ exp(-x[i,y_i]) * sum_j exp(x[i,j]) - 1 ] )
// (the j == y_i term of sum_j exp(x[i,j]-pos) is exactly 1, so subtract it)

#define NCLS      340
#define NCLS4     85          // 340 / 4, row stride 1360 B is 16B-aligned
#define GRID      1184
#define BLOCK     256
#define WPB       (BLOCK / 32)

__device__ double g_partials[GRID];

__global__ __launch_bounds__(BLOCK)
void lsep_partial_kernel(const float* __restrict__ x,
                         const int* __restrict__ tgt,   // int32 (JAX x64 disabled)
                         int B)
{
    const int lane   = threadIdx.x & 31;
    const int wlocal = threadIdx.x >> 5;
    const int wglob  = blockIdx.x * WPB + wlocal;
    const int wtotal = gridDim.x * WPB;

    double acc = 0.0;

    for (int row = wglob; row < B; row += wtotal) {
        const float4* r = reinterpret_cast<const float4*>(x + (size_t)row * NCLS);

        float s = 0.0f;
        // 85 float4 per row: lanes 0..31 cover i = lane, lane+32, lane+64 (<85)
        #pragma unroll 3
        for (int i = lane; i < NCLS4; i += 32) {
            float4 v = r[i];
            s += __expf(v.x) + __expf(v.y) + __expf(v.z) + __expf(v.w);
        }

        // warp reduce s
        #pragma unroll
        for (int o = 16; o; o >>= 1)
            s += __shfl_xor_sync(0xffffffffu, s, o);

        if (lane == 0) {
            int y = tgt[row];
            y = min(max(y, 0), NCLS - 1);            // defensive clamp
            float pos = x[(size_t)row * NCLS + y];   // L1/L2 hit: row just read
            acc += (double)s * exp(-(double)pos) - 1.0;
        }
    }

    __shared__ double sacc[WPB];
    if (lane == 0) sacc[wlocal] = acc;
    __syncthreads();

    if (threadIdx.x == 0) {
        double t = 0.0;
        #pragma unroll
        for (int i = 0; i < WPB; i++) t += sacc[i];
        g_partials[blockIdx.x] = t;
    }
}

__global__ __launch_bounds__(256)
void lsep_final_kernel(float* __restrict__ out)
{
    __shared__ double s[256];
    double t = 0.0;
    for (int i = threadIdx.x; i < GRID; i += 256)
        t += g_partials[i];
    s[threadIdx.x] = t;
    __syncthreads();
    #pragma unroll
    for (int o = 128; o; o >>= 1) {
        if (threadIdx.x < o) s[threadIdx.x] += s[threadIdx.x + o];
        __syncthreads();
    }
    if (threadIdx.x == 0)
        out[0] = (float)log1p(s[0]);
}

extern "C" void kernel_launch(void* const* d_in, const int* in_sizes, int n_in,
                              void* d_out, int out_size)
{
    const float* x   = (const float*)d_in[0];
    const int*   tgt = (const int*)d_in[1];
    float*       out = (float*)d_out;

    int B = in_sizes[0] / NCLS;   // 65536

    lsep_partial_kernel<<<GRID, BLOCK>>>(x, tgt, B);
    lsep_final_kernel<<<1, 256>>>(out);
}

// round 3
// speedup vs baseline: 4.1163x; 4.1163x over previous
#include <cuda_runtime.h>

// LSEP loss: log1p( sum_i [ exp(-x[i,y_i]) * sum_j exp(x[i,j]) ] - B )
// (the j == y_i term of exp(x-pos) is exactly 1 per row -> subtract B once)
//
// Single fused kernel. Each warp owns a row per iteration; each lane keeps a
// PARTIAL row sum and multiplies by exp(-pos) itself (uniform broadcast load,
// L1 hit). No per-row shuffles, no fp64 exp, no lane-0 serialization.
// Final reduction via last-block-done with a self-resetting atomic counter
// (graph-replay safe, deterministic order).

#define NCLS   340
#define NCLS4  85            // 340/4; row stride 1360 B is 16B-aligned
#define GRID   1184          // 148 SMs * 8 blocks
#define BLOCK  256
#define WPB    (BLOCK / 32)

__device__ double       g_partials[GRID];
__device__ unsigned int g_count = 0;     // auto-resets via atomicInc wrap

__global__ __launch_bounds__(BLOCK)
void lsep_fused_kernel(const float* __restrict__ x,
                       const int*   __restrict__ tgt,
                       float*       __restrict__ out,
                       int B)
{
    const int lane   = threadIdx.x & 31;
    const int wlocal = threadIdx.x >> 5;
    const int wglob  = blockIdx.x * WPB + wlocal;
    const int wtotal = GRID * WPB;

    double acc = 0.0;

    for (int row = wglob; row < B; row += wtotal) {
        const float4* r = reinterpret_cast<const float4*>(x + (size_t)row * NCLS);

        int y = tgt[row];                        // issues early, indep of r[]

        float4 v0 = r[lane];
        float4 v1 = r[lane + 32];
        float4 v2;                               // lanes 0..20 only (85 = 2*32+21)
        if (lane < NCLS4 - 64) v2 = r[lane + 64];

        float s = __expf(v0.x) + __expf(v0.y) + __expf(v0.z) + __expf(v0.w)
                + __expf(v1.x) + __expf(v1.y) + __expf(v1.z) + __expf(v1.w);
        if (lane < NCLS4 - 64)
            s += __expf(v2.x) + __expf(v2.y) + __expf(v2.z) + __expf(v2.w);

        float pos = x[(size_t)row * NCLS + y];   // uniform broadcast, L1 hit
        acc += (double)(s * __expf(-pos));       // lane-partial contribution
    }

    // ---- block reduction (deterministic) ----
    #pragma unroll
    for (int o = 16; o; o >>= 1)
        acc += __shfl_xor_sync(0xffffffffu, acc, o);

    __shared__ double sacc[WPB];
    if (lane == 0) sacc[wlocal] = acc;
    __syncthreads();

    __shared__ bool is_last;
    if (threadIdx.x == 0) {
        double t = 0.0;
        #pragma unroll
        for (int i = 0; i < WPB; i++) t += sacc[i];
        g_partials[blockIdx.x] = t;
        __threadfence();
        unsigned int old = atomicInc(&g_count, GRID - 1);  // wraps to 0 after GRID
        is_last = (old == GRID - 1);
    }
    __syncthreads();

    // ---- last block: final reduce (order fixed -> deterministic) ----
    if (is_last) {
        __threadfence();
        __shared__ double sfin[BLOCK];
        double t = 0.0;
        for (int i = threadIdx.x; i < GRID; i += BLOCK)
            t += g_partials[i];
        sfin[threadIdx.x] = t;
        __syncthreads();
        #pragma unroll
        for (int o = BLOCK / 2; o; o >>= 1) {
            if (threadIdx.x < o) sfin[threadIdx.x] += sfin[threadIdx.x + o];
            __syncthreads();
        }
        if (threadIdx.x == 0)
            out[0] = (float)log1p(sfin[0] - (double)B);
    }
}

extern "C" void kernel_launch(void* const* d_in, const int* in_sizes, int n_in,
                              void* d_out, int out_size)
{
    const float* x   = (const float*)d_in[0];
    const int*   tgt = (const int*)d_in[1];
    float*       out = (float*)d_out;

    int B = in_sizes[0] / NCLS;   // 65536

    lsep_fused_kernel<<<GRID, BLOCK>>>(x, tgt, out, B);
}

// round 4
// speedup vs baseline: 4.5316x; 1.1009x over previous
#include <cuda_runtime.h>

// LSEP loss: log1p( sum_i [ exp(-x[i,y_i]) * sum_j exp(x[i,j]) ] - B )
// Each warp processes a PAIR of adjacent rows per iteration (contiguous
// 2720 B, 6 front-batched LDG.128 -> high MLP). Lane-partial trick: each
// lane scales its partial row sum by exp(-pos) itself; summing over lanes
// reconstructs the row term. Targets for the NEXT pair are prefetched one
// iteration ahead (int2: rows are adjacent) so the pos gathers issue in
// parallel with the row loads instead of serially after tgt arrives.
// Single kernel; last-block-done final reduce (self-resetting counter ->
// graph-replay safe, deterministic order).

#define NCLS   340
#define NCLS4  85            // 340/4; row stride 1360 B is 16B-aligned
#define GRID   592           // 148 SMs * 4 CTAs (regs ~45 -> 4 resident)
#define BLOCK  256
#define WPB    (BLOCK / 32)

__device__ double       g_partials[GRID];
__device__ unsigned int g_count = 0;     // wraps via atomicInc -> replay-safe

__device__ __forceinline__ float exp4(float4 v) {
    return __expf(v.x) + __expf(v.y) + __expf(v.z) + __expf(v.w);
}

__global__ __launch_bounds__(BLOCK, 4)
void lsep_fused_kernel(const float* __restrict__ x,
                       const int*   __restrict__ tgt,
                       float*       __restrict__ out,
                       int B)
{
    const int lane   = threadIdx.x & 31;
    const int wlocal = threadIdx.x >> 5;
    const int wglob  = blockIdx.x * WPB + wlocal;
    const int wtotal = GRID * WPB;

    const int nPairs = B >> 1;
    const int2* __restrict__ t2 = (const int2*)tgt;

    double acc = 0.0;

    int p = wglob;
    if (p < nPairs) {
        int2 y = t2[p];                       // prologue target prefetch
        for (;;) {
            const float* xA = x + (size_t)(p * 2) * NCLS;
            const float* xB = xA + NCLS;

            // pos gathers issue FIRST (y already resident from last iter)
            float posA = __ldg(xA + (unsigned)y.x % NCLS);
            float posB = __ldg(xB + (unsigned)y.y % NCLS);

            const float4* rA = (const float4*)xA;
            const float4* rB = (const float4*)xB;
            float4 a0 = rA[lane], a1 = rA[lane + 32];
            float4 b0 = rB[lane], b1 = rB[lane + 32];
            float4 a2, b2;
            const bool tail = lane < (NCLS4 - 64);   // lanes 0..20
            if (tail) { a2 = rA[lane + 64]; b2 = rB[lane + 64]; }

            // prefetch next pair's targets while loads are in flight
            int pn = p + wtotal;
            const bool more = pn < nPairs;
            int2 yn;
            if (more) yn = t2[pn];

            float sA = exp4(a0) + exp4(a1);
            float sB = exp4(b0) + exp4(b1);
            if (tail) { sA += exp4(a2); sB += exp4(b2); }

            acc += (double)(sA * __expf(-posA))
                 + (double)(sB * __expf(-posB));

            if (!more) break;
            p = pn; y = yn;
        }
    }

    // ---- block reduction (deterministic) ----
    #pragma unroll
    for (int o = 16; o; o >>= 1)
        acc += __shfl_xor_sync(0xffffffffu, acc, o);

    __shared__ double sacc[WPB];
    if (lane == 0) sacc[wlocal] = acc;
    __syncthreads();

    __shared__ bool is_last;
    if (threadIdx.x == 0) {
        double t = 0.0;
        #pragma unroll
        for (int i = 0; i < WPB; i++) t += sacc[i];
        g_partials[blockIdx.x] = t;
        __threadfence();
        unsigned int old = atomicInc(&g_count, GRID - 1);  // wraps to 0
        is_last = (old == GRID - 1);
    }
    __syncthreads();

    // ---- last block: deterministic final reduce + log1p ----
    if (is_last) {
        __threadfence();
        __shared__ double sfin[BLOCK];
        double t = 0.0;
        for (int i = threadIdx.x; i < GRID; i += BLOCK)
            t += g_partials[i];
        sfin[threadIdx.x] = t;
        __syncthreads();
        #pragma unroll
        for (int o = BLOCK / 2; o; o >>= 1) {
            if (threadIdx.x < o) sfin[threadIdx.x] += sfin[threadIdx.x + o];
            __syncthreads();
        }
        if (threadIdx.x == 0)
            out[0] = (float)log1p(sfin[0] - (double)B);
    }
}

extern "C" void kernel_launch(void* const* d_in, const int* in_sizes, int n_in,
                              void* d_out, int out_size)
{
    const float* x   = (const float*)d_in[0];
    const int*   tgt = (const int*)d_in[1];
    float*       out = (float*)d_out;

    int B = in_sizes[0] / NCLS;   // 65536

    lsep_fused_kernel<<<GRID, BLOCK>>>(x, tgt, out, B);
}

// round 5
// speedup vs baseline: 4.5385x; 1.0015x over previous
#include <cuda_runtime.h>
#include <cstdint>

// LSEP loss: log1p( sum_i [ exp(-x[i,y_i]) * sum_j exp(x[i,j]) ] - B )
//
// Bulk-async smem pipeline: rows are contiguous, so each CTA streams 16-row
// stages (21760 B) into a 4-deep smem ring via cp.async.bulk + mbarrier
// complete_tx (MLP decoupled from registers). 8 consumer warps each take 2
// rows/stage from smem (conflict-free LDS.128); pos is read from smem too,
// killing the serial gmem gather. Lane-partial trick as before; -1 per row
// folded into a single -B. Last-block-done final reduce (self-resetting
// counter -> graph-replay safe, deterministic order).

#define NCLS        340
#define NCLS4       85
#define ROW_BYTES   1360
#define RPS         16                       // rows per stage
#define STAGE_BYTES (RPS * ROW_BYTES)        // 21760
#define STAGES      4
#define BLOCK       256
#define WPB         8
#define GRID        296                      // 148 SMs * 2 CTAs
#define SMEM_TOTAL  (STAGES * STAGE_BYTES + STAGES * 8)   // data + mbarriers

__device__ double       g_partials[GRID];
__device__ unsigned int g_count = 0;         // wraps via atomicInc -> replay-safe

__device__ __forceinline__ uint32_t smem_u32(const void* p) {
    uint32_t a;
    asm("{ .reg .u64 t; cvta.to.shared.u64 t, %1; cvt.u32.u64 %0, t; }"
        : "=r"(a) : "l"(p));
    return a;
}

__device__ __forceinline__ void mbar_init(uint32_t mbar, uint32_t cnt) {
    asm volatile("mbarrier.init.shared.b64 [%0], %1;" :: "r"(mbar), "r"(cnt) : "memory");
}

__device__ __forceinline__ void bulk_load(uint32_t dst_smem, const void* gsrc,
                                          uint32_t bytes, uint32_t mbar) {
    asm volatile(
        "mbarrier.arrive.expect_tx.shared.b64 _, [%0], %1;\n\t"
        "cp.async.bulk.shared::cta.global.mbarrier::complete_tx::bytes "
        "[%2], [%3], %1, [%0];"
        :: "r"(mbar), "r"(bytes), "r"(dst_smem), "l"(gsrc) : "memory");
}

__device__ __forceinline__ void mbar_wait(uint32_t mbar, uint32_t parity) {
    uint32_t done;
    asm volatile(
        "{\n\t.reg .pred p;\n\t"
        "mbarrier.try_wait.parity.acquire.cta.shared::cta.b64 p, [%1], %2;\n\t"
        "selp.b32 %0, 1, 0, p;\n\t}"
        : "=r"(done) : "r"(mbar), "r"(parity) : "memory");
    if (!done) {
        asm volatile(
            "{\n\t.reg .pred P1;\n\t"
            "W_%=:\n\t"
            "mbarrier.try_wait.parity.acquire.cta.shared::cta.b64 P1, [%0], %1, 0x989680;\n\t"
            "@P1 bra.uni D_%=;\n\t"
            "bra.uni W_%=;\n\t"
            "D_%=:\n\t}"
            :: "r"(mbar), "r"(parity) : "memory");
    }
}

__device__ __forceinline__ float exp4(float4 v) {
    return __expf(v.x) + __expf(v.y) + __expf(v.z) + __expf(v.w);
}

__global__ __launch_bounds__(BLOCK, 2)
void lsep_pipe_kernel(const float* __restrict__ x,
                      const int*   __restrict__ tgt,
                      float*       __restrict__ out,
                      int B)
{
    extern __shared__ char smem[];
    const int tid  = threadIdx.x;
    const int lane = tid & 31;
    const int warp = tid >> 5;

    const uint32_t sbase = smem_u32(smem);
    const uint32_t mbar0 = sbase + STAGES * STAGE_BYTES;

    if (tid == 0) {
        #pragma unroll
        for (int s = 0; s < STAGES; s++) mbar_init(mbar0 + 8 * s, 1);
    }
    __syncthreads();

    const int nstages_total = B / RPS;                        // 4096
    const int nit = (nstages_total - blockIdx.x + GRID - 1) / GRID;

    if (tid == 0) {
        asm volatile("fence.proxy.async.shared::cta;" ::: "memory");
        const int pre = nit < STAGES ? nit : STAGES;
        for (int j = 0; j < pre; j++) {
            int g = blockIdx.x + j * GRID;
            bulk_load(sbase + (j % STAGES) * STAGE_BYTES,
                      x + (size_t)g * RPS * NCLS, STAGE_BYTES,
                      mbar0 + 8 * (j % STAGES));
        }
    }

    double acc = 0.0;

    for (int i = 0; i < nit; i++) {
        const int g    = blockIdx.x + i * GRID;
        const int slot = i & (STAGES - 1);
        const uint32_t parity = (i / STAGES) & 1;

        const int rowA = g * RPS + warp * 2;
        int2 y = *(const int2*)(tgt + rowA);                  // gmem, issued pre-wait
        y.x = min(max(y.x, 0), NCLS - 1);
        y.y = min(max(y.y, 0), NCLS - 1);

        mbar_wait(mbar0 + 8 * slot, parity);

        const char* sl = smem + slot * STAGE_BYTES;
        const float* fA = (const float*)(sl + (warp * 2) * ROW_BYTES);
        const float* fB = fA + NCLS;
        const float4* rA = (const float4*)fA;
        const float4* rB = (const float4*)fB;

        const float posA = fA[y.x];                           // smem broadcast
        const float posB = fB[y.y];

        float4 a0 = rA[lane], a1 = rA[lane + 32];
        float4 b0 = rB[lane], b1 = rB[lane + 32];
        float sA = exp4(a0) + exp4(a1);
        float sB = exp4(b0) + exp4(b1);
        if (lane < NCLS4 - 64) {                              // lanes 0..20
            sA += exp4(rA[lane + 64]);
            sB += exp4(rB[lane + 64]);
        }

        acc += (double)(sA * __expf(-posA) + sB * __expf(-posB));

        __syncthreads();                                      // all done with slot
        if (tid == 0 && i + STAGES < nit) {
            int gn = blockIdx.x + (i + STAGES) * GRID;
            bulk_load(sbase + slot * STAGE_BYTES,
                      x + (size_t)gn * RPS * NCLS, STAGE_BYTES,
                      mbar0 + 8 * slot);
        }
    }

    // ---- block reduction (deterministic) ----
    #pragma unroll
    for (int o = 16; o; o >>= 1)
        acc += __shfl_xor_sync(0xffffffffu, acc, o);

    __shared__ double sacc[WPB];
    __shared__ bool   is_last;
    if (lane == 0) sacc[warp] = acc;
    __syncthreads();

    if (tid == 0) {
        double t = 0.0;
        #pragma unroll
        for (int i = 0; i < WPB; i++) t += sacc[i];
        g_partials[blockIdx.x] = t;
        __threadfence();
        unsigned int old = atomicInc(&g_count, GRID - 1);     // wraps to 0
        is_last = (old == GRID - 1);
    }
    __syncthreads();

    if (is_last) {
        __threadfence();
        __shared__ double sfin[BLOCK];
        double t = 0.0;
        for (int i = tid; i < GRID; i += BLOCK) t += g_partials[i];
        sfin[tid] = t;
        __syncthreads();
        #pragma unroll
        for (int o = BLOCK / 2; o; o >>= 1) {
            if (tid < o) sfin[tid] += sfin[tid + o];
            __syncthreads();
        }
        if (tid == 0) out[0] = (float)log1p(sfin[0] - (double)B);
    }
}

extern "C" void kernel_launch(void* const* d_in, const int* in_sizes, int n_in,
                              void* d_out, int out_size)
{
    const float* x   = (const float*)d_in[0];
    const int*   tgt = (const int*)d_in[1];
    float*       out = (float*)d_out;

    int B = in_sizes[0] / NCLS;   // 65536 (divisible by RPS)

    cudaFuncSetAttribute(lsep_pipe_kernel,
                         cudaFuncAttributeMaxDynamicSharedMemorySize, SMEM_TOTAL);
    lsep_pipe_kernel<<<GRID, BLOCK, SMEM_TOTAL>>>(x, tgt, out, B);
}

// round 6
// speedup vs baseline: 4.5939x; 1.0122x over previous
#include <cuda_runtime.h>

// LSEP loss: log1p( sum_i [ exp(-x[i,y_i]) * sum_j exp(x[i,j]) ] - B )
//
// Register double-buffered pipeline: while a warp computes the exps of row i,
// row i+1's three float4 loads and its pos gather are already in flight, and
// tgt is prefetched TWO iterations ahead so the y -> pos dependency never
// serializes. Keeps ~1360B continuously in flight per warp -> HBM latency
// hidden by Little's law at 24+ warps/SM. Lane-partial trick (each lane
// scales its own partial row sum by exp(-pos)); per-row -1 folded into -B.
// Fused last-block-done reduce (self-resetting counter -> graph-replay safe,
// deterministic order).

#define NCLS   340
#define NCLS4  85            // 340/4; row stride 1360 B is 16B-aligned
#define GRID   592           // 148 SMs * 4
#define BLOCK  256
#define WPB    (BLOCK / 32)

__device__ double       g_partials[GRID];
__device__ unsigned int g_count = 0;     // wraps via atomicInc -> replay-safe

__device__ __forceinline__ float exp4(float4 v) {
    return __expf(v.x) + __expf(v.y) + __expf(v.z) + __expf(v.w);
}

__global__ __launch_bounds__(BLOCK)
void lsep_pipe_kernel(const float* __restrict__ x,
                      const int*   __restrict__ tgt,
                      float*       __restrict__ out,
                      int B)
{
    const int lane   = threadIdx.x & 31;
    const int warp   = threadIdx.x >> 5;
    const int wglob  = blockIdx.x * WPB + warp;
    const int wtotal = GRID * WPB;

    const bool tail = lane < (NCLS4 - 64);   // lanes 0..20 own the 3rd float4

    double acc = 0.0;

    int row = wglob;
    if (row < B) {
        // ---- prologue: fill the pipeline ----
        const float4* rc = (const float4*)(x + (size_t)row * NCLS);
        float4 c0 = rc[lane];
        float4 c1 = rc[lane + 32];
        float4 c2 = c0;
        if (tail) c2 = rc[lane + 64];

        int yc = tgt[row];
        yc = min(max(yc, 0), NCLS - 1);
        float posc = __ldg(x + (size_t)row * NCLS + yc);

        int r1 = row + wtotal;
        int yn = 0;
        if (r1 < B) {
            yn = tgt[r1];
            yn = min(max(yn, 0), NCLS - 1);
        }

        for (;;) {
            const int rn1 = row + wtotal;          // next row (data+pos)
            const int rn2 = row + 2 * wtotal;      // next-next (target only)
            const bool more = rn1 < B;

            float4 n0, n1, n2;
            float  posn = 0.0f;
            if (more) {
                const float4* rn = (const float4*)(x + (size_t)rn1 * NCLS);
                n0 = rn[lane];
                n1 = rn[lane + 32];
                n2 = n0;
                if (tail) n2 = rn[lane + 64];
                posn = __ldg(x + (size_t)rn1 * NCLS + yn);   // yn resident
            }
            int yn2 = 0;
            if (rn2 < B) {
                yn2 = tgt[rn2];
                yn2 = min(max(yn2, 0), NCLS - 1);
            }

            // ---- compute current row while next row's loads fly ----
            float s = exp4(c0) + exp4(c1);
            if (tail) s += exp4(c2);
            acc += (double)(s * __expf(-posc));

            if (!more) break;
            c0 = n0; c1 = n1; c2 = n2;
            posc = posn; yn = yn2;
            row = rn1;
        }
    }

    // ---- block reduction (deterministic) ----
    #pragma unroll
    for (int o = 16; o; o >>= 1)
        acc += __shfl_xor_sync(0xffffffffu, acc, o);

    __shared__ double sacc[WPB];
    __shared__ bool   is_last;
    if (lane == 0) sacc[warp] = acc;
    __syncthreads();

    if (threadIdx.x == 0) {
        double t = 0.0;
        #pragma unroll
        for (int i = 0; i < WPB; i++) t += sacc[i];
        g_partials[blockIdx.x] = t;
        __threadfence();
        unsigned int old = atomicInc(&g_count, GRID - 1);   // wraps to 0
        is_last = (old == GRID - 1);
    }
    __syncthreads();

    // ---- last block: deterministic final reduce + log1p ----
    if (is_last) {
        __threadfence();
        __shared__ double sfin[BLOCK];
        double t = 0.0;
        for (int i = threadIdx.x; i < GRID; i += BLOCK)
            t += g_partials[i];
        sfin[threadIdx.x] = t;
        __syncthreads();
        #pragma unroll
        for (int o = BLOCK / 2; o; o >>= 1) {
            if (threadIdx.x < o) sfin[threadIdx.x] += sfin[threadIdx.x + o];
            __syncthreads();
        }
        if (threadIdx.x == 0)
            out[0] = (float)log1p(sfin[0] - (double)B);
    }
}

extern "C" void kernel_launch(void* const* d_in, const int* in_sizes, int n_in,
                              void* d_out, int out_size)
{
    const float* x   = (const float*)d_in[0];
    const int*   tgt = (const int*)d_in[1];
    float*       out = (float*)d_out;

    int B = in_sizes[0] / NCLS;   // 65536

    lsep_pipe_kernel<<<GRID, BLOCK>>>(x, tgt, out, B);
}